// round 4
// baseline (speedup 1.0000x reference)
#include <cuda_runtime.h>
#include <math.h>
#include <float.h>

#define L_    2
#define B_    32
#define S_    512
#define D_    512
#define H_    8
#define DH_   64
#define DFF_  2048
#define KIDX_ 5
#define M_    (B_*S_)   // 16384 rows

// ---------------- scratch (device globals; no runtime allocation) ----------------
__device__ float g_x[B_*S_*D_];
__device__ float g_y[B_*S_*D_];
__device__ float g_qk[B_*S_*D_];
__device__ float g_v[B_*S_*D_];
__device__ float g_attn[B_*S_*D_];
__device__ float g_tmp[B_*S_*D_];
__device__ float g_ff[(size_t)B_*S_*DFF_];

// ---------------- x = q_emb + pos ; y = i_emb + pos ----------------
__global__ void add_pos_kernel(const float* __restrict__ q,
                               const float* __restrict__ ie,
                               const float* __restrict__ pos) {
    int idx = blockIdx.x * blockDim.x + threadIdx.x;   // over B*S*D
    int sd  = idx % (S_ * D_);
    float p = pos[sd];
    g_x[idx] = q[idx]  + p;
    g_y[idx] = ie[idx] + p;
}

// ---------------- C[M,N] = A[M,K] @ W[K,N] + bias (optional ReLU) ----------------
// 64x64 tile, k-tile 16, 256 threads, 4x4 per-thread microtile.
__global__ __launch_bounds__(256)
void gemm_kernel(const float* __restrict__ A, const float* __restrict__ W,
                 const float* __restrict__ bias, float* __restrict__ C,
                 int K, int N, int relu) {
    __shared__ float As[16][65];
    __shared__ float Ws[16][65];
    int tid = threadIdx.x;
    int tx = tid & 15, ty = tid >> 4;
    int bm = blockIdx.y * 64, bn = blockIdx.x * 64;
    float acc[4][4] = {};

    for (int k0 = 0; k0 < K; k0 += 16) {
        #pragma unroll
        for (int e = 0; e < 4; e++) {
            int li = tid + e * 256;            // 0..1023
            int r = li >> 4, c = li & 15;      // A tile: 64 rows x 16 cols
            As[c][r] = A[(size_t)(bm + r) * K + k0 + c];
            int r2 = li >> 6, c2 = li & 63;    // W tile: 16 rows x 64 cols
            Ws[r2][c2] = W[(size_t)(k0 + r2) * N + bn + c2];
        }
        __syncthreads();
        #pragma unroll
        for (int kk = 0; kk < 16; kk++) {
            float a[4], b[4];
            #pragma unroll
            for (int i = 0; i < 4; i++) a[i] = As[kk][ty + 16 * i];
            #pragma unroll
            for (int j = 0; j < 4; j++) b[j] = Ws[kk][tx + 16 * j];
            #pragma unroll
            for (int i = 0; i < 4; i++)
                #pragma unroll
                for (int j = 0; j < 4; j++)
                    acc[i][j] += a[i] * b[j];
        }
        __syncthreads();
    }

    #pragma unroll
    for (int i = 0; i < 4; i++) {
        int m = bm + ty + 16 * i;
        #pragma unroll
        for (int j = 0; j < 4; j++) {
            int n = bn + tx + 16 * j;
            float v = acc[i][j] + bias[n];
            if (relu) v = fmaxf(v, 0.f);
            C[(size_t)m * N + n] = v;
        }
    }
}

// ---------------- sparse causal attention ----------------
// One warp per query row i; 8 consecutive rows of the same (b,h) per block so
// K/V tiles are loaded to SMEM once per block (8x traffic reduction).
__global__ __launch_bounds__(256)
void attn_kernel(const float* __restrict__ qk, const float* __restrict__ v,
                 float* __restrict__ out) {
    __shared__ float tile[32][65];    // K tile, then reused as V tile
    __shared__ float probs[8][S_];
    __shared__ float qs[8][64];

    int w = threadIdx.y, lane = threadIdx.x;
    int blk = blockIdx.x;
    int bh  = blk >> 6;              // S/8 = 64 blocks per (b,h)
    int i0  = (blk & 63) * 8;
    int b = bh >> 3, h = bh & 7;
    int i = i0 + w;                  // this warp's query row
    int tid = w * 32 + lane;

    size_t qoff = ((size_t)(b * S_ + i) * D_ + h * DH_);
    qs[w][lane]      = qk[qoff + lane];
    qs[w][lane + 32] = qk[qoff + lane + 32];

    int nkeys  = i0 + 7;             // max keys needed by any warp in block
    int ntiles = (nkeys + 31) >> 5;
    __syncthreads();

    // ---- phase 1: scores (q . k_j / 8) ----
    for (int t = 0; t < ntiles; t++) {
        int j0 = t << 5;
        #pragma unroll
        for (int e = 0; e < 8; e++) {
            int li = tid + e * 256;
            int jr = li >> 6, dd = li & 63;
            tile[jr][dd] = qk[((size_t)(b * S_ + j0 + jr) * D_ + h * DH_) + dd];
        }
        __syncthreads();
        int j = j0 + lane;
        if (j < i) {
            float s = 0.f;
            #pragma unroll
            for (int dd = 0; dd < 64; dd++) s += qs[w][dd] * tile[lane][dd];
            probs[w][j] = s * 0.125f;
        }
        __syncthreads();
    }

    // ---- phase 2: softmax; phase 3: top-k re-softmax (warp-local) ----
    if (i > 0) {
        float mx = -FLT_MAX;
        for (int j = lane; j < i; j += 32) mx = fmaxf(mx, probs[w][j]);
        for (int o = 16; o; o >>= 1) mx = fmaxf(mx, __shfl_xor_sync(~0u, mx, o));
        float sum = 0.f;
        for (int j = lane; j < i; j += 32) {
            float e = expf(probs[w][j] - mx);
            probs[w][j] = e; sum += e;
        }
        for (int o = 16; o; o >>= 1) sum += __shfl_xor_sync(~0u, sum, o);
        float inv = 1.f / sum;
        for (int j = lane; j < i; j += 32) probs[w][j] *= inv;

        if (i > KIDX_) {
            // find 5th-largest prob (counting multiplicity): iterative max extraction
            float cur = FLT_MAX;
            int kept = 0;
            float m1 = -FLT_MAX;   // top-1 prob (for re-softmax stability)
            for (int it = 0; it < KIDX_ && kept < KIDX_; it++) {
                float lm = -FLT_MAX;
                for (int j = lane; j < i; j += 32) {
                    float p = probs[w][j];
                    if (p < cur && p > lm) lm = p;
                }
                for (int o = 16; o; o >>= 1) lm = fmaxf(lm, __shfl_xor_sync(~0u, lm, o));
                int lc = 0;
                for (int j = lane; j < i; j += 32) if (probs[w][j] == lm) lc++;
                for (int o = 16; o; o >>= 1) lc += __shfl_xor_sync(~0u, lc, o);
                if (it == 0) m1 = lm;
                kept += lc;
                cur = lm;
            }
            float thresh = cur;
            // re-softmax OF THE PROBABILITIES over the kept set
            float sum2 = 0.f;
            for (int j = lane; j < i; j += 32) {
                float p = probs[w][j];
                float wt = (p >= thresh) ? expf(p - m1) : 0.f;
                probs[w][j] = wt; sum2 += wt;
            }
            for (int o = 16; o; o >>= 1) sum2 += __shfl_xor_sync(~0u, sum2, o);
            float inv2 = 1.f / sum2;
            for (int j = lane; j < i; j += 32) probs[w][j] *= inv2;
        }
    }

    // ---- phase 4: out = probs @ V (V tiled through SMEM) ----
    float acc0 = 0.f, acc1 = 0.f;
    for (int t = 0; t < ntiles; t++) {
        int j0 = t << 5;
        __syncthreads();      // previous tile use complete before overwrite
        #pragma unroll
        for (int e = 0; e < 8; e++) {
            int li = tid + e * 256;
            int jr = li >> 6, dd = li & 63;
            tile[jr][dd] = v[((size_t)(b * S_ + j0 + jr) * D_ + h * DH_) + dd];
        }
        __syncthreads();
        int jend = i - j0; if (jend > 32) jend = 32;
        for (int jj = 0; jj < jend; jj++) {
            float wt = probs[w][j0 + jj];
            acc0 += wt * tile[jj][lane];
            acc1 += wt * tile[jj][lane + 32];
        }
    }
    size_t ooff = ((size_t)(b * S_ + i) * D_ + h * DH_);
    out[ooff + lane]      = (i == 0) ? 0.f : acc0;   // zero_pad row 0
    out[ooff + lane + 32] = (i == 0) ? 0.f : acc1;
}

// ---------------- out = LayerNorm(xin + delta) * g + b ----------------
__global__ __launch_bounds__(128)
void resid_ln_kernel(const float* __restrict__ xin, const float* __restrict__ delta,
                     const float* __restrict__ g, const float* __restrict__ bta,
                     float* __restrict__ out) {
    __shared__ float red[4];
    int row = blockIdx.x;
    int t = threadIdx.x;            // 128 threads, 4 elems each
    float v[4];
    float s = 0.f;
    #pragma unroll
    for (int e = 0; e < 4; e++) {
        int d = t + e * 128;
        v[e] = xin[(size_t)row * D_ + d] + delta[(size_t)row * D_ + d];
        s += v[e];
    }
    for (int o = 16; o; o >>= 1) s += __shfl_xor_sync(~0u, s, o);
    if ((t & 31) == 0) red[t >> 5] = s;
    __syncthreads();
    s = red[0] + red[1] + red[2] + red[3];
    float mean = s * (1.f / D_);

    float sq = 0.f;
    #pragma unroll
    for (int e = 0; e < 4; e++) { float dd = v[e] - mean; sq += dd * dd; }
    __syncthreads();                // red reuse
    for (int o = 16; o; o >>= 1) sq += __shfl_xor_sync(~0u, sq, o);
    if ((t & 31) == 0) red[t >> 5] = sq;
    __syncthreads();
    sq = red[0] + red[1] + red[2] + red[3];
    float rstd = rsqrtf(sq * (1.f / D_) + 1e-5f);

    #pragma unroll
    for (int e = 0; e < 4; e++) {
        int d = t + e * 128;
        out[(size_t)row * D_ + d] = (v[e] - mean) * rstd * g[d] + bta[d];
    }
}

// ---------------- launcher ----------------
extern "C" void kernel_launch(void* const* d_in, const int* in_sizes, int n_in,
                              void* d_out, int out_size) {
    const float* question = (const float*)d_in[0];
    const float* inter    = (const float*)d_in[1];
    const float* pos      = (const float*)d_in[2];
    const float* Wk  = (const float*)d_in[3];
    const float* bk  = (const float*)d_in[4];
    const float* Wv  = (const float*)d_in[5];
    const float* bv  = (const float*)d_in[6];
    const float* Wo  = (const float*)d_in[7];
    const float* bo  = (const float*)d_in[8];
    const float* ln1g = (const float*)d_in[9];
    const float* ln1b = (const float*)d_in[10];
    const float* W1  = (const float*)d_in[11];
    const float* b1  = (const float*)d_in[12];
    const float* W2  = (const float*)d_in[13];
    const float* b2  = (const float*)d_in[14];
    const float* ln2g = (const float*)d_in[15];
    const float* ln2b = (const float*)d_in[16];

    float *x, *y, *qkb, *vb, *attnb, *tmpb, *ffb;
    cudaGetSymbolAddress((void**)&x,     g_x);
    cudaGetSymbolAddress((void**)&y,     g_y);
    cudaGetSymbolAddress((void**)&qkb,   g_qk);
    cudaGetSymbolAddress((void**)&vb,    g_v);
    cudaGetSymbolAddress((void**)&attnb, g_attn);
    cudaGetSymbolAddress((void**)&tmpb,  g_tmp);
    cudaGetSymbolAddress((void**)&ffb,   g_ff);

    add_pos_kernel<<<(B_ * S_ * D_) / 256, 256>>>(question, inter, pos);

    for (int l = 0; l < L_; l++) {
        const float* Wkl = Wk + (size_t)l * D_ * D_;
        const float* Wvl = Wv + (size_t)l * D_ * D_;
        const float* Wol = Wo + (size_t)l * D_ * D_;
        const float* W1l = W1 + (size_t)l * D_ * DFF_;
        const float* W2l = W2 + (size_t)l * DFF_ * D_;

        dim3 gD(D_ / 64, M_ / 64);       // N=512 output
        dim3 gF(DFF_ / 64, M_ / 64);     // N=2048 output

        gemm_kernel<<<gD, 256>>>(x, Wkl, bk + l * D_, qkb, D_, D_, 0);
        gemm_kernel<<<gD, 256>>>(y, Wvl, bv + l * D_, vb,  D_, D_, 0);
        attn_kernel<<<B_ * H_ * (S_ / 8), dim3(32, 8)>>>(qkb, vb, attnb);
        gemm_kernel<<<gD, 256>>>(attnb, Wol, bo + l * D_, tmpb, D_, D_, 0);
        resid_ln_kernel<<<M_, 128>>>(x, tmpb, ln1g + l * D_, ln1b + l * D_, x);
        gemm_kernel<<<gF, 256>>>(x, W1l, b1 + l * DFF_, ffb, D_, DFF_, 1);
        gemm_kernel<<<gD, 256>>>(ffb, W2l, b2 + l * D_, tmpb, DFF_, D_, 0);
        float* lnout = (l == L_ - 1) ? (float*)d_out : x;
        resid_ln_kernel<<<M_, 128>>>(x, tmpb, ln2g + l * D_, ln2b + l * D_, lnout);
    }
}